// round 2
// baseline (speedup 1.0000x reference)
#include <cuda_runtime.h>
#include <cstddef>

// Problem constants
#define CI 256
#define CO 128
#define NX 16          // input spatial extent
#define YD 33          // intermediate y spatial extent
#define YD2 (33*33)    // 1089
#define YD3 (33*33*33) // 35937

// Intermediate y [8][128][33][33][33] and transposed weights [27][256][128]
__device__ float g_y[8 * 128 * YD3];        // ~147 MB
__device__ float g_wt[27 * CI * CO];        // ~3.5 MB

// ---------------------------------------------------------------------------
// Weight prep: g_wt[(j*CI + ci)*CO + co] = w[(co*CI + ci)*27 + j]
// Writes coalesced; one-time scattered reads are tiny (884736 elements).
// ---------------------------------------------------------------------------
__global__ void wprep_kernel(const float* __restrict__ w) {
    int i = blockIdx.x * 256 + threadIdx.x;
    if (i >= 27 * CI * CO) return;
    int co = i & (CO - 1);
    int r  = i >> 7;
    int ci = r & (CI - 1);
    int j  = r >> 8;
    g_wt[i] = __ldg(&w[(co * CI + ci) * 27 + j]);
}

// ---------------------------------------------------------------------------
// Stage 1: fractionally-strided conv, decomposed by output parity.
//   y[2q+s] per axis:  s==0 (even): w[0]*x[q-1] + w[2]*x[q]
//                      s==1 (odd):  w[1]*x[q]
// Template <SA,SB,SC> = parity per axis -> compile-time tap structure.
// Block tile: 4(a) x 4(b) x 8(c) q-positions x all 128 co.
// 256 threads: lane -> (b = lane>>3, c = lane&7), warp-id -> 16-co group,
// each thread accumulates acc[4 a][16 co].
// ---------------------------------------------------------------------------
template <int SA, int SB, int SC>
__global__ void __launch_bounds__(256, 2)
stage1_kernel(const float* __restrict__ x) {
    constexpr int NTA = SA ? 1 : 2, NTB = SB ? 1 : 2, NTC = SC ? 1 : 2;
    constexpr int NT  = NTA * NTB * NTC;            // taps per voxel
    constexpr int EA  = SA ? 16 : 17;               // output extent (q) per axis
    constexpr int EB  = SB ? 16 : 17;
    constexpr int EC  = SC ? 16 : 17;
    constexpr int WSA = SA ? 4 : 5;                 // x window per axis
    constexpr int WSB = SB ? 4 : 5;
    constexpr int WSC = SC ? 8 : 9;
    constexpr int TLB = SB ? 4 : 5;                 // tile counts (grid decode)
    constexpr int TLC = SC ? 2 : 3;

    __shared__ float Xs[4][WSA][WSB][WSC];
    __shared__ float Ws[4][NT][CO];

    const int n   = blockIdx.y;
    const int bid = blockIdx.x;
    const int tct = bid % TLC;
    const int tbt = (bid / TLC) % TLB;
    const int tat = bid / (TLC * TLB);
    const int q0a = tat * 4, q0b = tbt * 4, q0c = tct * 8;

    const int tid  = threadIdx.x;
    const int lane = tid & 31;
    const int co0  = (tid >> 5) * 16;   // warp-uniform -> Ws broadcast
    const int bpos = lane >> 3;         // 0..3
    const int cpos = lane & 7;          // 0..7

    const float* xn = x + (size_t)n * CI * (NX * NX * NX);

    float acc[4][16];
    #pragma unroll
    for (int a = 0; a < 4; a++)
        #pragma unroll
        for (int u = 0; u < 16; u++) acc[a][u] = 0.0f;

    for (int ci0 = 0; ci0 < CI; ci0 += 4) {
        __syncthreads();
        // ---- fill x window (zero-padded at borders) ----
        constexpr int XE = 4 * WSA * WSB * WSC;
        for (int e = tid; e < XE; e += 256) {
            int c  = e % WSC; int r = e / WSC;
            int b  = r % WSB; r /= WSB;
            int a  = r % WSA; int cc = r / WSA;
            int xa = q0a - (SA ? 0 : 1) + a;
            int xb = q0b - (SB ? 0 : 1) + b;
            int xc = q0c - (SC ? 0 : 1) + c;
            float v = 0.0f;
            if ((unsigned)xa < 16u && (unsigned)xb < 16u && (unsigned)xc < 16u)
                v = __ldg(xn + (size_t)(ci0 + cc) * 4096 + xa * 256 + xb * 16 + xc);
            Xs[cc][a][b][c] = v;
        }
        // ---- fill weights for this group's taps (coalesced over co) ----
        constexpr int WE = 4 * NT * CO;
        for (int e = tid; e < WE; e += 256) {
            int co = e & (CO - 1);
            int r  = e >> 7;
            int tp = r % NT; int cc = r / NT;
            int tcc = tp % NTC;
            int tbb = (tp / NTC) % NTB;
            int taa = tp / (NTC * NTB);
            int wa = SA ? 1 : 2 * taa;
            int wb = SB ? 1 : 2 * tbb;
            int wc = SC ? 1 : 2 * tcc;
            Ws[cc][tp][co] =
                g_wt[(size_t)((wa * 3 + wb) * 3 + wc) * (CI * CO) + (ci0 + cc) * CO + co];
        }
        __syncthreads();

        // ---- FMA core: per (ci, tap): 4 x-LDS + 16 w-LDS(broadcast) -> 64 FMA
        #pragma unroll
        for (int cc = 0; cc < 4; cc++) {
            #pragma unroll
            for (int tp = 0; tp < NT; tp++) {
                const int tcc = tp % NTC;
                const int tbb = (tp / NTC) % NTB;
                const int taa = tp / (NTC * NTB);
                float xv[4];
                #pragma unroll
                for (int a = 0; a < 4; a++)
                    xv[a] = Xs[cc][a + taa][bpos + tbb][cpos + tcc];
                #pragma unroll
                for (int u = 0; u < 16; u++) {
                    float wv = Ws[cc][tp][co0 + u];
                    #pragma unroll
                    for (int a = 0; a < 4; a++)
                        acc[a][u] = fmaf(xv[a], wv, acc[a][u]);
                }
            }
        }
    }

    // ---- store to y[n][co][2qa+SA][2qb+SB][2qc+SC] ----
    const int qb = q0b + bpos, qc = q0c + cpos;
    if (qb < EB && qc < EC) {
        const int tb2 = 2 * qb + SB, tc2 = 2 * qc + SC;
        #pragma unroll
        for (int a = 0; a < 4; a++) {
            int qa = q0a + a;
            if (qa < EA) {
                int ta2 = 2 * qa + SA;
                size_t base = (size_t)(n * CO + co0) * YD3 + ta2 * YD2 + tb2 * YD + tc2;
                #pragma unroll
                for (int u = 0; u < 16; u++)
                    g_y[base + (size_t)u * YD3] = acc[a][u];
            }
        }
    }
}

// ---------------------------------------------------------------------------
// Stage 2: separable FIR [0.25,0.75,0.75,0.25] per axis, pad(1,1), + bias.
// out[u] = sum_d k[d] * y[u-1+d] along each axis (kernel symmetric).
// Block: one (n, co, 8x8x8 output tile); 11^3 y window in smem, 3 passes.
// ---------------------------------------------------------------------------
__global__ void __launch_bounds__(256)
stage2_kernel(const float* __restrict__ bias, float* __restrict__ out) {
    __shared__ float ys[11 * 11 * 11];
    __shared__ float t1[11 * 11 * 8];
    __shared__ float t2[11 * 8 * 8];

    const int t   = blockIdx.x;          // 0..63
    const int u0c = (t & 3) * 8;
    const int u0b = ((t >> 2) & 3) * 8;
    const int u0a = (t >> 4) * 8;
    const int co  = blockIdx.y;
    const int n   = blockIdx.z;
    const int tid = threadIdx.x;

    const float* yb = g_y + (size_t)(n * CO + co) * YD3;

    for (int e = tid; e < 1331; e += 256) {
        int c = e % 11; int r = e / 11;
        int b = r % 11; int a = r / 11;
        int ta2 = u0a - 1 + a, tb2 = u0b - 1 + b, tc2 = u0c - 1 + c;
        float v = 0.0f;
        if ((unsigned)ta2 < 33u && (unsigned)tb2 < 33u && (unsigned)tc2 < 33u)
            v = yb[(size_t)ta2 * YD2 + tb2 * YD + tc2];
        ys[e] = v;
    }
    __syncthreads();

    // pass over c: 11 x 11 x 8
    for (int e = tid; e < 11 * 11 * 8; e += 256) {
        int c = e & 7; int r = e >> 3;
        int b = r % 11; int a = r / 11;
        const float* p = &ys[(a * 11 + b) * 11 + c];
        t1[e] = 0.25f * (p[0] + p[3]) + 0.75f * (p[1] + p[2]);
    }
    __syncthreads();

    // pass over b: 11 x 8 x 8
    for (int e = tid; e < 11 * 8 * 8; e += 256) {
        int c = e & 7; int b = (e >> 3) & 7; int a = e >> 6;
        const float* p = &t1[(a * 11 + b) * 8 + c];
        t2[e] = 0.25f * (p[0] + p[3 * 8]) + 0.75f * (p[8] + p[2 * 8]);
    }
    __syncthreads();

    const float bv = __ldg(&bias[co]);
    // pass over a: 8 x 8 x 8, write out
    for (int e = tid; e < 8 * 8 * 8; e += 256) {
        int c = e & 7; int b = (e >> 3) & 7; int a = e >> 6;
        const float* p = &t2[(a * 8 + b) * 8 + c];
        float v = 0.25f * (p[0] + p[3 * 64]) + 0.75f * (p[64] + p[2 * 64]) + bv;
        out[(size_t)(n * CO + co) * 32768 +
            (size_t)(u0a + a) * 1024 + (u0b + b) * 32 + (u0c + c)] = v;
    }
}

// ---------------------------------------------------------------------------
extern "C" void kernel_launch(void* const* d_in, const int* in_sizes, int n_in,
                              void* d_out, int out_size) {
    (void)in_sizes; (void)n_in; (void)out_size;
    const float* x    = (const float*)d_in[0];
    const float* w    = (const float*)d_in[1];
    const float* bias = (const float*)d_in[2];
    float* out        = (float*)d_out;

    wprep_kernel<<<(27 * CI * CO + 255) / 256, 256>>>(w);

    stage1_kernel<0, 0, 0><<<dim3(5 * 5 * 3, 8), 256>>>(x);
    stage1_kernel<0, 0, 1><<<dim3(5 * 5 * 2, 8), 256>>>(x);
    stage1_kernel<0, 1, 0><<<dim3(5 * 4 * 3, 8), 256>>>(x);
    stage1_kernel<0, 1, 1><<<dim3(5 * 4 * 2, 8), 256>>>(x);
    stage1_kernel<1, 0, 0><<<dim3(4 * 5 * 3, 8), 256>>>(x);
    stage1_kernel<1, 0, 1><<<dim3(4 * 5 * 2, 8), 256>>>(x);
    stage1_kernel<1, 1, 0><<<dim3(4 * 4 * 3, 8), 256>>>(x);
    stage1_kernel<1, 1, 1><<<dim3(4 * 4 * 2, 8), 256>>>(x);

    stage2_kernel<<<dim3(64, CO, 8), 256>>>(bias, out);
}